// round 1
// baseline (speedup 1.0000x reference)
#include <cuda_runtime.h>
#include <math.h>

// Problem: theta [B=4] (degrees), image [C=3, H=80, W=80] -> out [B, C, H, W].
// Reference builds a dense [B, N, N] tent-weight matrix; the tent max(0,1-|d|)
// has support <= 2 integer taps per axis, so the matmul is exactly bilinear
// interpolation with zero weight for taps outside [0, W-1] / [0, H-1].

#define B_ 4
#define C_ 3
#define H_ 80
#define W_ 80

__global__ __launch_bounds__(256) void rot_bilinear_kernel(
    const float* __restrict__ theta,   // [B]
    const float* __restrict__ image,   // [C, H, W]
    float* __restrict__ out)           // [B, C, H, W]
{
    const int t = blockIdx.x * blockDim.x + threadIdx.x;  // one thread per (b, y, x)
    const int total = B_ * H_ * W_;
    if (t >= total) return;

    const int x = t % W_;
    const int y = (t / W_) % H_;
    const int b = t / (H_ * W_);

    const float cx = (W_ - 1) * 0.5f;
    const float cy = (H_ - 1) * 0.5f;

    // deg2rad + rotation
    const float th = theta[b] * 0.017453292519943295f;  // pi/180
    float s, c;
    __sincosf(th, &s, &c);
    // Use precise sin/cos to match reference numerics (rel_err budget 1e-3 is
    // generous, but __sincosf fast-path has ~2^-22 abs error which is fine;
    // still, prefer exact intrinsics):
    s = sinf(th);
    c = cosf(th);

    const float x_rel = (float)x - cx;
    const float y_rel = (float)y - cy;

    const float sx = fmaf(c, x_rel, fmaf(s, y_rel, cx));   // cos*x + sin*y + cx
    const float sy = fmaf(-s, x_rel, fmaf(c, y_rel, cy));  // -sin*x + cos*y + cy

    // Bilinear taps with zero weight outside the grid (matches truncated tent sum)
    const float fx0 = floorf(sx);
    const float fy0 = floorf(sy);
    const int ix0 = (int)fx0;
    const int iy0 = (int)fy0;
    const int ix1 = ix0 + 1;
    const int iy1 = iy0 + 1;
    const float ax = sx - fx0;   // weight of ix1
    const float ay = sy - fy0;   // weight of iy1

    float wx0 = 1.0f - ax, wx1 = ax;
    float wy0 = 1.0f - ay, wy1 = ay;
    if (ix0 < 0 || ix0 >= W_) wx0 = 0.0f;
    if (ix1 < 0 || ix1 >= W_) wx1 = 0.0f;
    if (iy0 < 0 || iy0 >= H_) wy0 = 0.0f;
    if (iy1 < 0 || iy1 >= H_) wy1 = 0.0f;

    // Clamp indices for safe loads (weight already zeroed when out of range)
    const int cx0 = min(max(ix0, 0), W_ - 1);
    const int cx1 = min(max(ix1, 0), W_ - 1);
    const int cy0 = min(max(iy0, 0), H_ - 1);
    const int cy1 = min(max(iy1, 0), H_ - 1);

    const float w00 = wy0 * wx0;
    const float w01 = wy0 * wx1;
    const float w10 = wy1 * wx0;
    const float w11 = wy1 * wx1;

    const int base00 = cy0 * W_ + cx0;
    const int base01 = cy0 * W_ + cx1;
    const int base10 = cy1 * W_ + cx0;
    const int base11 = cy1 * W_ + cx1;

    #pragma unroll
    for (int ch = 0; ch < C_; ch++) {
        const float* img = image + ch * (H_ * W_);
        const float v = w00 * __ldg(img + base00)
                      + w01 * __ldg(img + base01)
                      + w10 * __ldg(img + base10)
                      + w11 * __ldg(img + base11);
        out[((b * C_ + ch) * H_ + y) * W_ + x] = v;
    }
}

extern "C" void kernel_launch(void* const* d_in, const int* in_sizes, int n_in,
                              void* d_out, int out_size) {
    const float* theta = (const float*)d_in[0];   // [4]
    const float* image = (const float*)d_in[1];   // [3, 80, 80]
    float* out = (float*)d_out;                   // [4, 3, 80, 80]

    const int total = B_ * H_ * W_;               // 25600 threads
    const int threads = 256;
    const int blocks = (total + threads - 1) / threads;  // 100
    rot_bilinear_kernel<<<blocks, threads>>>(theta, image, out);
}